// round 1
// baseline (speedup 1.0000x reference)
#include <cuda_runtime.h>
#include <math.h>

#define BB 4
#define NN 1024
#define MM 1024
#define DD 512
#define EPSI 0.1f
#define INV_EPS 10.0f
#define NITER 20
#define ERR_THRESH_TOTAL 0.4f   /* 0.1 * B, since err = sum_i.mean_b = total/B */

// ---- device scratch (allocation-free: __device__ globals) ----
__device__ float g_C[BB*NN*MM];   // cost matrix
__device__ float g_K[BB*NN*MM];   // exp(-C/eps)
__device__ float g_nx[BB*NN];
__device__ float g_ny[BB*MM];
__device__ float g_u [BB*NN];
__device__ float g_eu[BB*NN];     // exp(u/eps)
__device__ float g_ev[BB*MM];     // exp(v/eps)
__device__ float g_err[NITER];

// ---------------------------------------------------------------------------
__global__ void init_kernel(float* __restrict__ out) {
    int t = threadIdx.x;
    for (int i = t; i < BB*NN; i += 256) { g_u[i] = 0.f; g_eu[i] = 1.f; g_ev[i] = 1.f; }
    if (t < NITER) g_err[t] = 0.f;
    if (t < BB)    out[t]   = 0.f;
}

// one block (128 threads) per row of x or y; grid = 2*BB*NN
__global__ void __launch_bounds__(128) norm_kernel(const float* __restrict__ x,
                                                   const float* __restrict__ y) {
    int r = blockIdx.x;
    const float* src;
    float* dst;
    if (r < BB*NN) { src = x + (size_t)r * DD;             dst = &g_nx[r]; }
    else           { src = y + (size_t)(r - BB*NN) * DD;   dst = &g_ny[r - BB*NN]; }
    float4 v = ((const float4*)src)[threadIdx.x];  // 512 floats = 128 float4
    float s = v.x*v.x + v.y*v.y + v.z*v.z + v.w*v.w;
    #pragma unroll
    for (int o = 16; o; o >>= 1) s += __shfl_xor_sync(0xffffffffu, s, o);
    __shared__ float ws[4];
    if ((threadIdx.x & 31) == 0) ws[threadIdx.x >> 5] = s;
    __syncthreads();
    if (threadIdx.x == 0) *dst = sqrtf(ws[0] + ws[1] + ws[2] + ws[3]);
}

// 128x128 tile, 256 threads, 8x8 per thread; NT GEMM (both operands K-major)
__global__ void __launch_bounds__(256) cost_kernel(const float* __restrict__ X,
                                                   const float* __restrict__ Y) {
    __shared__ float As[16][132];
    __shared__ float Bs[16][132];
    int b    = blockIdx.z;
    int row0 = blockIdx.y * 128;
    int col0 = blockIdx.x * 128;
    const float* A  = X + (size_t)b * NN * DD;
    const float* Bm = Y + (size_t)b * MM * DD;
    int tid  = threadIdx.x;
    int tk4  = tid & 3;        // k-group (float4 along D)
    int rowL = tid >> 2;       // 0..63
    int ty   = tid >> 4;       // 0..15 -> rows ty*8..+7
    int tx   = tid & 15;       // 0..15 -> cols tx*8..+7

    float acc[8][8];
    #pragma unroll
    for (int i = 0; i < 8; i++)
        #pragma unroll
        for (int j = 0; j < 8; j++) acc[i][j] = 0.f;

    for (int k0 = 0; k0 < DD; k0 += 16) {
        #pragma unroll
        for (int h = 0; h < 2; h++) {
            int rr = rowL + h * 64;
            float4 av = *(const float4*)(A  + (size_t)(row0 + rr) * DD + k0 + tk4 * 4);
            float4 bv = *(const float4*)(Bm + (size_t)(col0 + rr) * DD + k0 + tk4 * 4);
            As[tk4*4+0][rr] = av.x; As[tk4*4+1][rr] = av.y;
            As[tk4*4+2][rr] = av.z; As[tk4*4+3][rr] = av.w;
            Bs[tk4*4+0][rr] = bv.x; Bs[tk4*4+1][rr] = bv.y;
            Bs[tk4*4+2][rr] = bv.z; Bs[tk4*4+3][rr] = bv.w;
        }
        __syncthreads();
        #pragma unroll
        for (int k = 0; k < 16; k++) {
            float a[8], bb[8];
            *(float4*)&a[0]  = *(const float4*)&As[k][ty*8];
            *(float4*)&a[4]  = *(const float4*)&As[k][ty*8+4];
            *(float4*)&bb[0] = *(const float4*)&Bs[k][tx*8];
            *(float4*)&bb[4] = *(const float4*)&Bs[k][tx*8+4];
            #pragma unroll
            for (int i = 0; i < 8; i++)
                #pragma unroll
                for (int j = 0; j < 8; j++)
                    acc[i][j] = fmaf(a[i], bb[j], acc[i][j]);
        }
        __syncthreads();
    }

    // epilogue: C = 1 - dot / max(nx*ny, 1e-8); K = exp(-C/eps)
    float nyv[8];
    #pragma unroll
    for (int j = 0; j < 8; j++) nyv[j] = g_ny[(b << 10) + col0 + tx*8 + j];

    #pragma unroll
    for (int i = 0; i < 8; i++) {
        int gr = row0 + ty*8 + i;
        float nx = g_nx[(b << 10) + gr];
        size_t base = ((size_t)b << 20) + ((size_t)gr << 10) + col0 + tx*8;
        #pragma unroll
        for (int jq = 0; jq < 2; jq++) {
            float cv[4], kv[4];
            #pragma unroll
            for (int j = 0; j < 4; j++) {
                float denom = fmaxf(nx * nyv[jq*4 + j], 1e-8f);
                cv[j] = 1.f - acc[i][jq*4 + j] / denom;
                kv[j] = __expf(-INV_EPS * cv[j]);
            }
            *(float4*)(g_C + base + jq*4) = make_float4(cv[0], cv[1], cv[2], cv[3]);
            *(float4*)(g_K + base + jq*4) = make_float4(kv[0], kv[1], kv[2], kv[3]);
        }
    }
}

// one block per (b, row i); r_i = sum_j K_ij * ev_j ; u update + err atomics
__global__ void __launch_bounds__(256) row_kernel(int iter) {
    __shared__ bool s_done;
    if (threadIdx.x == 0) {
        bool d = false;
        for (int t = 0; t < iter; t++) d |= (g_err[t] < ERR_THRESH_TOTAL);
        s_done = d;
    }
    __syncthreads();
    if (s_done) return;

    int r = blockIdx.x;       // 0..4095
    int b = r >> 10;
    const float4* Krow = (const float4*)(g_K + ((size_t)r << 10));
    const float4* evp  = (const float4*)(g_ev + (b << 10));
    float4 kv = Krow[threadIdx.x];
    float4 e  = evp[threadIdx.x];
    float s = kv.x*e.x + kv.y*e.y + kv.z*e.z + kv.w*e.w;
    #pragma unroll
    for (int o = 16; o; o >>= 1) s += __shfl_xor_sync(0xffffffffu, s, o);
    __shared__ float ws[8];
    if ((threadIdx.x & 31) == 0) ws[threadIdx.x >> 5] = s;
    __syncthreads();
    if (threadIdx.x == 0) {
        float tot = ws[0]+ws[1]+ws[2]+ws[3]+ws[4]+ws[5]+ws[6]+ws[7];
        const float log_mu = logf(1.0f / (float)NN + 1e-8f);
        float u_old = g_u[r];
        float u_new = EPSI * log_mu - EPSI * __logf(tot);
        atomicAdd(&g_err[iter], fabsf(u_new - u_old));
        g_u[r]  = u_new;
        g_eu[r] = __expf(u_new * INV_EPS);
    }
}

// block = (b, 32 columns); 256 threads = 32 cols x 8 row-groups
__global__ void __launch_bounds__(256) col_kernel(int iter, const float* __restrict__ nu) {
    __shared__ bool s_done;
    if (threadIdx.x == 0) {
        bool d = false;
        for (int t = 0; t < iter; t++) d |= (g_err[t] < ERR_THRESH_TOTAL);
        s_done = d;
    }
    __syncthreads();
    if (s_done) return;

    int blk = blockIdx.x;          // 0..127
    int b   = blk >> 5;
    int j0  = (blk & 31) * 32;
    int c   = threadIdx.x & 31;
    int g   = threadIdx.x >> 5;    // 0..7
    const float* Kb  = g_K  + ((size_t)b << 20);
    const float* eub = g_eu + (b << 10);
    float s = 0.f;
    #pragma unroll 4
    for (int i = g; i < NN; i += 8)
        s += Kb[((size_t)i << 10) + j0 + c] * eub[i];
    __shared__ float red[8][33];
    red[g][c] = s;
    __syncthreads();
    if (g == 0) {
        float tot = 0.f;
        #pragma unroll
        for (int q = 0; q < 8; q++) tot += red[q][c];
        int j = (b << 10) + j0 + c;
        float v_new = EPSI * __logf(nu[j] + 1e-8f) - EPSI * __logf(tot);
        g_ev[j] = __expf(v_new * INV_EPS);
    }
}

// cost[b] = sum_ij C * K * eu_i * ev_j ; block = (b, 16 rows)
__global__ void __launch_bounds__(256) final_kernel(float* __restrict__ out) {
    int blk = blockIdx.x;          // 0..BB*64-1
    int b   = blk >> 6;
    int i0  = (blk & 63) << 4;
    const float4* Cb  = (const float4*)(g_C + ((size_t)b << 20));
    const float4* Kb  = (const float4*)(g_K + ((size_t)b << 20));
    const float4* evp = (const float4*)(g_ev + (b << 10));
    float4 e = evp[threadIdx.x];
    float s = 0.f;
    for (int i = i0; i < i0 + 16; i++) {
        float4 c  = Cb[(i << 8) + threadIdx.x];
        float4 kk = Kb[(i << 8) + threadIdx.x];
        float rs = c.x*kk.x*e.x + c.y*kk.y*e.y + c.z*kk.z*e.z + c.w*kk.w*e.w;
        s += g_eu[(b << 10) + i] * rs;
    }
    #pragma unroll
    for (int o = 16; o; o >>= 1) s += __shfl_xor_sync(0xffffffffu, s, o);
    __shared__ float ws[8];
    if ((threadIdx.x & 31) == 0) ws[threadIdx.x >> 5] = s;
    __syncthreads();
    if (threadIdx.x == 0) {
        float tot = ws[0]+ws[1]+ws[2]+ws[3]+ws[4]+ws[5]+ws[6]+ws[7];
        atomicAdd(out + b, tot);
    }
}

// ---------------------------------------------------------------------------
extern "C" void kernel_launch(void* const* d_in, const int* in_sizes, int n_in,
                              void* d_out, int out_size) {
    const float* x  = (const float*)d_in[0];   // [B,N,D]
    const float* y  = (const float*)d_in[1];   // [B,M,D]
    const float* nu = (const float*)d_in[2];   // [B,M]
    float* out = (float*)d_out;                // [B]

    init_kernel<<<1, 256>>>(out);
    norm_kernel<<<2 * BB * NN, 128>>>(x, y);
    cost_kernel<<<dim3(MM/128, NN/128, BB), 256>>>(x, y);
    for (int it = 0; it < NITER; it++) {
        row_kernel<<<BB * NN, 256>>>(it);
        col_kernel<<<BB * (MM/32), 256>>>(it, nu);
    }
    final_kernel<<<BB * 64, 256>>>(out);
}

// round 4
// speedup vs baseline: 1.2134x; 1.2134x over previous
#include <cuda_runtime.h>
#include <stdint.h>
#include <math.h>

#define BB 4
#define NN 1024
#define MM 1024
#define DD 512
#define EPSI 0.1f
#define INV_EPS 10.0f
#define NITER 20
#define ERR_THRESH_TOTAL 0.4f   /* 0.1 * B, since err = total/B */

// ---- device scratch (allocation-free: __device__ globals) ----
__device__ float g_K[BB*NN*MM];   // exp(-C/eps)
__device__ float g_nx[BB*NN];
__device__ float g_ny[BB*MM];
__device__ float g_u [BB*NN];
__device__ float g_eu[BB*NN];     // exp(u/eps)
__device__ float g_ev[BB*MM];     // exp(v/eps)
__device__ float g_err[NITER];

// ---------------------------------------------------------------------------
__global__ void init_kernel(float* __restrict__ out) {
    int t = threadIdx.x;
    for (int i = t; i < BB*NN; i += 256) { g_u[i] = 0.f; g_eu[i] = 1.f; g_ev[i] = 1.f; }
    if (t < NITER) g_err[t] = 0.f;
    if (t < BB)    out[t]   = 0.f;
}

__global__ void __launch_bounds__(128) norm_kernel(const float* __restrict__ x,
                                                   const float* __restrict__ y) {
    int r = blockIdx.x;
    const float* src;
    float* dst;
    if (r < BB*NN) { src = x + (size_t)r * DD;             dst = &g_nx[r]; }
    else           { src = y + (size_t)(r - BB*NN) * DD;   dst = &g_ny[r - BB*NN]; }
    float4 v = ((const float4*)src)[threadIdx.x];
    float s = v.x*v.x + v.y*v.y + v.z*v.z + v.w*v.w;
    #pragma unroll
    for (int o = 16; o; o >>= 1) s += __shfl_xor_sync(0xffffffffu, s, o);
    __shared__ float ws[4];
    if ((threadIdx.x & 31) == 0) ws[threadIdx.x >> 5] = s;
    __syncthreads();
    if (threadIdx.x == 0) *dst = sqrtf(ws[0] + ws[1] + ws[2] + ws[3]);
}

// ---------------------------------------------------------------------------
// tf32 mma.sync GEMM: CTA 128x128, 8 warps of 32x64, K chunks of 32 floats,
// double-buffered smem with k-permuted layout so fragment pairs are LDS.64.
// Smem tile: 128 rows x 36 floats (32 data + 4 pad).  perm(k) = 2*(k&3)+(k>>2).
// ---------------------------------------------------------------------------
#define TSTRIDE 36
#define TILE_FLOATS (128*TSTRIDE)   // 4608

__global__ void __launch_bounds__(256) gemm_kernel(const float* __restrict__ X,
                                                   const float* __restrict__ Y) {
    extern __shared__ float sm[];   // 4 tiles: A0 B0 A1 B1 = 18432 floats = 72KB
    __shared__ float s_ny[128];

    const int tid  = threadIdx.x;
    const int lane = tid & 31;
    const int wid  = tid >> 5;
    const int wm   = wid & 3;          // 0..3  -> rows wm*32..+31
    const int wn   = wid >> 2;         // 0..1  -> cols wn*64..+63
    const int g    = lane >> 2;        // groupID 0..7
    const int tig  = lane & 3;         // threadInGroup

    const int b    = blockIdx.z;
    const int row0 = blockIdx.y << 7;
    const int col0 = blockIdx.x << 7;

    uint32_t* smA[2] = { (uint32_t*)sm,                (uint32_t*)(sm + 2*TILE_FLOATS) };
    uint32_t* smB[2] = { (uint32_t*)(sm + TILE_FLOATS), (uint32_t*)(sm + 3*TILE_FLOATS) };

    if (tid < 128) s_ny[tid] = g_ny[(b << 10) + col0 + tid];

    // per-thread global load geometry: 1024 float4 per tile, 4 per thread
    const float* Abase = X + ((size_t)b << 19) + ((size_t)row0 << 9);
    const float* Bbase = Y + ((size_t)b << 19) + ((size_t)col0 << 9);
    const float* gA[4]; const float* gB[4];
    int sBase[4];
    #pragma unroll
    for (int q = 0; q < 4; q++) {
        int idx = tid + (q << 8);
        int row = idx >> 3;          // 0..127
        int c4  = idx & 7;           // which float4 along k (0..7)
        gA[q] = Abase + ((size_t)row << 9) + (c4 << 2);
        gB[q] = Bbase + ((size_t)row << 9) + (c4 << 2);
        sBase[q] = row * TSTRIDE + ((c4 >> 1) << 3) + (c4 & 1);  // perm base; elems at +0,2,4,6
    }

    float acc[2][8][4];
    #pragma unroll
    for (int mt = 0; mt < 2; mt++)
        #pragma unroll
        for (int nt = 0; nt < 8; nt++)
            #pragma unroll
            for (int j = 0; j < 4; j++) acc[mt][nt][j] = 0.f;

    // prologue: fill buffer 0 (k0 = 0)
    {
        #pragma unroll
        for (int q = 0; q < 4; q++) {
            float4 av = *(const float4*)(gA[q]);
            float4 bv = *(const float4*)(gB[q]);
            uint32_t r0,r1,r2,r3;
            asm("cvt.rna.tf32.f32 %0,%1;" : "=r"(r0) : "f"(av.x));
            asm("cvt.rna.tf32.f32 %0,%1;" : "=r"(r1) : "f"(av.y));
            asm("cvt.rna.tf32.f32 %0,%1;" : "=r"(r2) : "f"(av.z));
            asm("cvt.rna.tf32.f32 %0,%1;" : "=r"(r3) : "f"(av.w));
            smA[0][sBase[q]+0]=r0; smA[0][sBase[q]+2]=r1; smA[0][sBase[q]+4]=r2; smA[0][sBase[q]+6]=r3;
            asm("cvt.rna.tf32.f32 %0,%1;" : "=r"(r0) : "f"(bv.x));
            asm("cvt.rna.tf32.f32 %0,%1;" : "=r"(r1) : "f"(bv.y));
            asm("cvt.rna.tf32.f32 %0,%1;" : "=r"(r2) : "f"(bv.z));
            asm("cvt.rna.tf32.f32 %0,%1;" : "=r"(r3) : "f"(bv.w));
            smB[0][sBase[q]+0]=r0; smB[0][sBase[q]+2]=r1; smB[0][sBase[q]+4]=r2; smB[0][sBase[q]+6]=r3;
        }
    }
    __syncthreads();

    for (int s = 0; s < 16; s++) {
        const int buf = s & 1;
        float4 pa[4], pb[4];
        if (s < 15) {
            int k0 = (s + 1) << 5;
            #pragma unroll
            for (int q = 0; q < 4; q++) {
                pa[q] = *(const float4*)(gA[q] + k0);
                pb[q] = *(const float4*)(gB[q] + k0);
            }
        }

        // compute 4 k-steps of 8 on this buffer
        #pragma unroll
        for (int k8 = 0; k8 < 4; k8++) {
            uint32_t a[2][4];
            #pragma unroll
            for (int mt = 0; mt < 2; mt++) {
                int r = wm*32 + mt*16 + g;
                uint2 lo = *(uint2*)&smA[buf][r*TSTRIDE       + k8*8 + 2*tig];
                uint2 hi = *(uint2*)&smA[buf][(r+8)*TSTRIDE   + k8*8 + 2*tig];
                a[mt][0] = lo.x; a[mt][2] = lo.y;   // A[r][k], A[r][k+4]
                a[mt][1] = hi.x; a[mt][3] = hi.y;   // A[r+8][k], A[r+8][k+4]
            }
            #pragma unroll
            for (int nt = 0; nt < 8; nt++) {
                int c = wn*64 + nt*8 + g;
                uint2 bb = *(uint2*)&smB[buf][c*TSTRIDE + k8*8 + 2*tig];
                #pragma unroll
                for (int mt = 0; mt < 2; mt++) {
                    asm volatile(
                        "mma.sync.aligned.m16n8k8.row.col.f32.tf32.tf32.f32 "
                        "{%0,%1,%2,%3}, {%4,%5,%6,%7}, {%8,%9}, {%0,%1,%2,%3};"
                        : "+f"(acc[mt][nt][0]), "+f"(acc[mt][nt][1]),
                          "+f"(acc[mt][nt][2]), "+f"(acc[mt][nt][3])
                        : "r"(a[mt][0]), "r"(a[mt][1]), "r"(a[mt][2]), "r"(a[mt][3]),
                          "r"(bb.x), "r"(bb.y));
                }
            }
        }
        __syncthreads();

        if (s < 15) {
            const int nb = buf ^ 1;
            #pragma unroll
            for (int q = 0; q < 4; q++) {
                uint32_t r0,r1,r2,r3;
                asm("cvt.rna.tf32.f32 %0,%1;" : "=r"(r0) : "f"(pa[q].x));
                asm("cvt.rna.tf32.f32 %0,%1;" : "=r"(r1) : "f"(pa[q].y));
                asm("cvt.rna.tf32.f32 %0,%1;" : "=r"(r2) : "f"(pa[q].z));
                asm("cvt.rna.tf32.f32 %0,%1;" : "=r"(r3) : "f"(pa[q].w));
                smA[nb][sBase[q]+0]=r0; smA[nb][sBase[q]+2]=r1; smA[nb][sBase[q]+4]=r2; smA[nb][sBase[q]+6]=r3;
                asm("cvt.rna.tf32.f32 %0,%1;" : "=r"(r0) : "f"(pb[q].x));
                asm("cvt.rna.tf32.f32 %0,%1;" : "=r"(r1) : "f"(pb[q].y));
                asm("cvt.rna.tf32.f32 %0,%1;" : "=r"(r2) : "f"(pb[q].z));
                asm("cvt.rna.tf32.f32 %0,%1;" : "=r"(r3) : "f"(pb[q].w));
                smB[nb][sBase[q]+0]=r0; smB[nb][sBase[q]+2]=r1; smB[nb][sBase[q]+4]=r2; smB[nb][sBase[q]+6]=r3;
            }
            __syncthreads();
        }
    }

    // epilogue: K = exp(-(1 - dot/max(nx*ny,1e-8))/eps)
    float nxv[2][2];
    #pragma unroll
    for (int mt = 0; mt < 2; mt++) {
        int r = row0 + wm*32 + mt*16 + g;
        nxv[mt][0] = g_nx[(b << 10) + r];
        nxv[mt][1] = g_nx[(b << 10) + r + 8];
    }
    float* Kb = g_K + ((size_t)b << 20);
    #pragma unroll
    for (int mt = 0; mt < 2; mt++) {
        #pragma unroll
        for (int nt = 0; nt < 8; nt++) {
            int col = wn*64 + nt*8 + 2*tig;
            float ny0 = s_ny[col], ny1 = s_ny[col + 1];
            int rlo = row0 + wm*32 + mt*16 + g;
            float2 vlo, vhi;
            {
                float d0 = fmaxf(nxv[mt][0]*ny0, 1e-8f);
                float d1 = fmaxf(nxv[mt][0]*ny1, 1e-8f);
                vlo.x = __expf(-INV_EPS * (1.f - acc[mt][nt][0] / d0));
                vlo.y = __expf(-INV_EPS * (1.f - acc[mt][nt][1] / d1));
                float e0 = fmaxf(nxv[mt][1]*ny0, 1e-8f);
                float e1 = fmaxf(nxv[mt][1]*ny1, 1e-8f);
                vhi.x = __expf(-INV_EPS * (1.f - acc[mt][nt][2] / e0));
                vhi.y = __expf(-INV_EPS * (1.f - acc[mt][nt][3] / e1));
            }
            *(float2*)(Kb + ((size_t)rlo       << 10) + col0 + col) = vlo;
            *(float2*)(Kb + ((size_t)(rlo + 8) << 10) + col0 + col) = vhi;
        }
    }
}

// one block per (b, row i); r_i = sum_j K_ij * ev_j ; u update + err atomics
__global__ void __launch_bounds__(256) row_kernel(int iter) {
    __shared__ bool s_done;
    if (threadIdx.x == 0) {
        bool d = false;
        for (int t = 0; t < iter; t++) d |= (g_err[t] < ERR_THRESH_TOTAL);
        s_done = d;
    }
    __syncthreads();
    if (s_done) return;

    int r = blockIdx.x;
    int b = r >> 10;
    const float4* Krow = (const float4*)(g_K + ((size_t)r << 10));
    const float4* evp  = (const float4*)(g_ev + (b << 10));
    float4 kv = Krow[threadIdx.x];
    float4 e  = evp[threadIdx.x];
    float s = kv.x*e.x + kv.y*e.y + kv.z*e.z + kv.w*e.w;
    #pragma unroll
    for (int o = 16; o; o >>= 1) s += __shfl_xor_sync(0xffffffffu, s, o);
    __shared__ float ws[8];
    if ((threadIdx.x & 31) == 0) ws[threadIdx.x >> 5] = s;
    __syncthreads();
    if (threadIdx.x == 0) {
        float tot = ws[0]+ws[1]+ws[2]+ws[3]+ws[4]+ws[5]+ws[6]+ws[7];
        const float log_mu = logf(1.0f / (float)NN + 1e-8f);
        float u_old = g_u[r];
        float u_new = EPSI * log_mu - EPSI * __logf(tot);
        atomicAdd(&g_err[iter], fabsf(u_new - u_old));
        g_u[r]  = u_new;
        g_eu[r] = __expf(u_new * INV_EPS);
    }
}

// block = (b, 32 columns); 256 threads = 32 cols x 8 row-groups
__global__ void __launch_bounds__(256) col_kernel(int iter, const float* __restrict__ nu) {
    __shared__ bool s_done;
    if (threadIdx.x == 0) {
        bool d = false;
        for (int t = 0; t < iter; t++) d |= (g_err[t] < ERR_THRESH_TOTAL);
        s_done = d;
    }
    __syncthreads();
    if (s_done) return;

    int blk = blockIdx.x;
    int b   = blk >> 5;
    int j0  = (blk & 31) * 32;
    int c   = threadIdx.x & 31;
    int g   = threadIdx.x >> 5;
    const float* Kb  = g_K  + ((size_t)b << 20);
    const float* eub = g_eu + (b << 10);
    float s = 0.f;
    #pragma unroll 4
    for (int i = g; i < NN; i += 8)
        s += Kb[((size_t)i << 10) + j0 + c] * eub[i];
    __shared__ float red[8][33];
    red[g][c] = s;
    __syncthreads();
    if (g == 0) {
        float tot = 0.f;
        #pragma unroll
        for (int q = 0; q < 8; q++) tot += red[q][c];
        int j = (b << 10) + j0 + c;
        float v_new = EPSI * __logf(nu[j] + 1e-8f) - EPSI * __logf(tot);
        g_ev[j] = __expf(v_new * INV_EPS);
    }
}

// cost[b] = sum_ij C * K * eu_i * ev_j with C = -eps*ln K ; block = (b, 16 rows)
__global__ void __launch_bounds__(256) final_kernel(float* __restrict__ out) {
    int blk = blockIdx.x;
    int b   = blk >> 6;
    int i0  = (blk & 63) << 4;
    const float4* Kb  = (const float4*)(g_K + ((size_t)b << 20));
    const float4* evp = (const float4*)(g_ev + (b << 10));
    float4 e = evp[threadIdx.x];
    float s = 0.f;
    for (int i = i0; i < i0 + 16; i++) {
        float4 kk = Kb[(i << 8) + threadIdx.x];
        float c0 = -EPSI * __logf(kk.x);
        float c1 = -EPSI * __logf(kk.y);
        float c2 = -EPSI * __logf(kk.z);
        float c3 = -EPSI * __logf(kk.w);
        float rs = c0*kk.x*e.x + c1*kk.y*e.y + c2*kk.z*e.z + c3*kk.w*e.w;
        s += g_eu[(b << 10) + i] * rs;
    }
    #pragma unroll
    for (int o = 16; o; o >>= 1) s += __shfl_xor_sync(0xffffffffu, s, o);
    __shared__ float ws[8];
    if ((threadIdx.x & 31) == 0) ws[threadIdx.x >> 5] = s;
    __syncthreads();
    if (threadIdx.x == 0) {
        float tot = ws[0]+ws[1]+ws[2]+ws[3]+ws[4]+ws[5]+ws[6]+ws[7];
        atomicAdd(out + b, tot);
    }
}

// ---------------------------------------------------------------------------
extern "C" void kernel_launch(void* const* d_in, const int* in_sizes, int n_in,
                              void* d_out, int out_size) {
    const float* x  = (const float*)d_in[0];   // [B,N,D]
    const float* y  = (const float*)d_in[1];   // [B,M,D]
    const float* nu = (const float*)d_in[2];   // [B,M]
    float* out = (float*)d_out;                // [B]

    const int dyn = 4 * TILE_FLOATS * 4;       // 73728 bytes
    cudaFuncSetAttribute(gemm_kernel, cudaFuncAttributeMaxDynamicSharedMemorySize, dyn);

    init_kernel<<<1, 256>>>(out);
    norm_kernel<<<2 * BB * NN, 128>>>(x, y);
    gemm_kernel<<<dim3(MM/128, NN/128, BB), 256, dyn>>>(x, y);
    for (int it = 0; it < NITER; it++) {
        row_kernel<<<BB * NN, 256>>>(it);
        col_kernel<<<BB * (MM/32), 256>>>(it, nu);
    }
    final_kernel<<<BB * 64, 256>>>(out);
}

// round 6
// speedup vs baseline: 2.1100x; 1.7389x over previous
#include <cuda_runtime.h>
#include <stdint.h>
#include <math.h>

#define BB 4
#define NN 1024
#define MM 1024
#define DD 512
#define EPSI 0.1f
#define INV_EPS 10.0f
#define NITER 20
#define ERR_THRESH_TOTAL 0.4f   /* 0.1 * B, since err = total/B */
#define GRID 128

// ---- device scratch (allocation-free: __device__ globals) ----
__device__ float g_K[BB*NN*MM];   // exp(-C/eps)
__device__ float g_nx[BB*NN];
__device__ float g_ny[BB*MM];
__device__ float g_u [BB*NN];
__device__ float g_eu[BB*NN];     // exp(u/eps)
__device__ float g_ev[BB*MM];     // exp(v/eps)
__device__ float g_err[NITER];
__device__ unsigned           g_bar_count = 0;
__device__ volatile unsigned  g_bar_gen   = 0;

// ---------------- grid-wide barrier (all GRID CTAs co-resident) ----------------
__device__ __forceinline__ void grid_sync() {
    __syncthreads();
    if (threadIdx.x == 0) {
        __threadfence();
        unsigned gen = g_bar_gen;
        if (atomicAdd(&g_bar_count, 1u) == GRID - 1) {
            g_bar_count = 0;
            __threadfence();
            g_bar_gen = gen + 1;
        } else {
            while (g_bar_gen == gen) __nanosleep(64);
        }
    }
    __syncthreads();
}

// ---------------------------------------------------------------------------
// tf32 mma.sync GEMM tile: CTA 128x128, 8 warps of 32x64, K chunks of 32,
// double-buffered smem, k-permuted layout (perm(k)=2(k&3)+(k>>2)) -> LDS.64.
// ---------------------------------------------------------------------------
#define TSTRIDE 36
#define TILE_FLOATS (128*TSTRIDE)   // 4608 floats per tile buffer

__device__ void gemm_tile(const float* __restrict__ X, const float* __restrict__ Y,
                          int b, int row0, int col0, float* sm, float* s_ny) {
    const int tid  = threadIdx.x;
    const int lane = tid & 31;
    const int wid  = tid >> 5;
    const int wm   = wid & 3;
    const int wn   = wid >> 2;
    const int g    = lane >> 2;
    const int tig  = lane & 3;

    uint32_t* smA[2] = { (uint32_t*)sm,                 (uint32_t*)(sm + 2*TILE_FLOATS) };
    uint32_t* smB[2] = { (uint32_t*)(sm + TILE_FLOATS), (uint32_t*)(sm + 3*TILE_FLOATS) };

    __syncthreads();   // previous tile's epilogue done before overwriting s_ny/buffers
    if (tid < 128) s_ny[tid] = __ldcg(&g_ny[(b << 10) + col0 + tid]);

    const float* Abase = X + ((size_t)b << 19) + ((size_t)row0 << 9);
    const float* Bbase = Y + ((size_t)b << 19) + ((size_t)col0 << 9);
    const float* gA[4]; const float* gB[4];
    int sBase[4];
    #pragma unroll
    for (int q = 0; q < 4; q++) {
        int idx = tid + (q << 8);
        int row = idx >> 3, c4 = idx & 7;
        gA[q] = Abase + ((size_t)row << 9) + (c4 << 2);
        gB[q] = Bbase + ((size_t)row << 9) + (c4 << 2);
        sBase[q] = row * TSTRIDE + ((c4 >> 1) << 3) + (c4 & 1);
    }

    float acc[2][8][4];
    #pragma unroll
    for (int mt = 0; mt < 2; mt++)
        #pragma unroll
        for (int nt = 0; nt < 8; nt++)
            #pragma unroll
            for (int j = 0; j < 4; j++) acc[mt][nt][j] = 0.f;

    // prologue: buffer 0
    #pragma unroll
    for (int q = 0; q < 4; q++) {
        float4 av = *(const float4*)(gA[q]);
        float4 bv = *(const float4*)(gB[q]);
        uint32_t r0,r1,r2,r3;
        asm("cvt.rna.tf32.f32 %0,%1;" : "=r"(r0) : "f"(av.x));
        asm("cvt.rna.tf32.f32 %0,%1;" : "=r"(r1) : "f"(av.y));
        asm("cvt.rna.tf32.f32 %0,%1;" : "=r"(r2) : "f"(av.z));
        asm("cvt.rna.tf32.f32 %0,%1;" : "=r"(r3) : "f"(av.w));
        smA[0][sBase[q]+0]=r0; smA[0][sBase[q]+2]=r1; smA[0][sBase[q]+4]=r2; smA[0][sBase[q]+6]=r3;
        asm("cvt.rna.tf32.f32 %0,%1;" : "=r"(r0) : "f"(bv.x));
        asm("cvt.rna.tf32.f32 %0,%1;" : "=r"(r1) : "f"(bv.y));
        asm("cvt.rna.tf32.f32 %0,%1;" : "=r"(r2) : "f"(bv.z));
        asm("cvt.rna.tf32.f32 %0,%1;" : "=r"(r3) : "f"(bv.w));
        smB[0][sBase[q]+0]=r0; smB[0][sBase[q]+2]=r1; smB[0][sBase[q]+4]=r2; smB[0][sBase[q]+6]=r3;
    }
    __syncthreads();

    for (int s = 0; s < 16; s++) {
        const int buf = s & 1;
        float4 pa[4], pb[4];
        if (s < 15) {
            int k0 = (s + 1) << 5;
            #pragma unroll
            for (int q = 0; q < 4; q++) {
                pa[q] = *(const float4*)(gA[q] + k0);
                pb[q] = *(const float4*)(gB[q] + k0);
            }
        }
        #pragma unroll
        for (int k8 = 0; k8 < 4; k8++) {
            uint32_t a[2][4];
            #pragma unroll
            for (int mt = 0; mt < 2; mt++) {
                int r = wm*32 + mt*16 + g;
                uint2 lo = *(uint2*)&smA[buf][r*TSTRIDE     + k8*8 + 2*tig];
                uint2 hi = *(uint2*)&smA[buf][(r+8)*TSTRIDE + k8*8 + 2*tig];
                a[mt][0] = lo.x; a[mt][2] = lo.y;
                a[mt][1] = hi.x; a[mt][3] = hi.y;
            }
            #pragma unroll
            for (int nt = 0; nt < 8; nt++) {
                int c = wn*64 + nt*8 + g;
                uint2 bb = *(uint2*)&smB[buf][c*TSTRIDE + k8*8 + 2*tig];
                #pragma unroll
                for (int mt = 0; mt < 2; mt++) {
                    asm volatile(
                        "mma.sync.aligned.m16n8k8.row.col.f32.tf32.tf32.f32 "
                        "{%0,%1,%2,%3}, {%4,%5,%6,%7}, {%8,%9}, {%0,%1,%2,%3};"
                        : "+f"(acc[mt][nt][0]), "+f"(acc[mt][nt][1]),
                          "+f"(acc[mt][nt][2]), "+f"(acc[mt][nt][3])
                        : "r"(a[mt][0]), "r"(a[mt][1]), "r"(a[mt][2]), "r"(a[mt][3]),
                          "r"(bb.x), "r"(bb.y));
                }
            }
        }
        __syncthreads();
        if (s < 15) {
            const int nb = buf ^ 1;
            #pragma unroll
            for (int q = 0; q < 4; q++) {
                uint32_t r0,r1,r2,r3;
                asm("cvt.rna.tf32.f32 %0,%1;" : "=r"(r0) : "f"(pa[q].x));
                asm("cvt.rna.tf32.f32 %0,%1;" : "=r"(r1) : "f"(pa[q].y));
                asm("cvt.rna.tf32.f32 %0,%1;" : "=r"(r2) : "f"(pa[q].z));
                asm("cvt.rna.tf32.f32 %0,%1;" : "=r"(r3) : "f"(pa[q].w));
                smA[nb][sBase[q]+0]=r0; smA[nb][sBase[q]+2]=r1; smA[nb][sBase[q]+4]=r2; smA[nb][sBase[q]+6]=r3;
                asm("cvt.rna.tf32.f32 %0,%1;" : "=r"(r0) : "f"(pb[q].x));
                asm("cvt.rna.tf32.f32 %0,%1;" : "=r"(r1) : "f"(pb[q].y));
                asm("cvt.rna.tf32.f32 %0,%1;" : "=r"(r2) : "f"(pb[q].z));
                asm("cvt.rna.tf32.f32 %0,%1;" : "=r"(r3) : "f"(pb[q].w));
                smB[nb][sBase[q]+0]=r0; smB[nb][sBase[q]+2]=r1; smB[nb][sBase[q]+4]=r2; smB[nb][sBase[q]+6]=r3;
            }
            __syncthreads();
        }
    }

    // epilogue: K = exp(-(1 - dot/max(nx*ny,1e-8))/eps)
    float nxv[2][2];
    #pragma unroll
    for (int mt = 0; mt < 2; mt++) {
        int r = row0 + wm*32 + mt*16 + g;
        nxv[mt][0] = __ldcg(&g_nx[(b << 10) + r]);
        nxv[mt][1] = __ldcg(&g_nx[(b << 10) + r + 8]);
    }
    float* Kb = g_K + ((size_t)b << 20);
    #pragma unroll
    for (int mt = 0; mt < 2; mt++) {
        #pragma unroll
        for (int nt = 0; nt < 8; nt++) {
            int col = wn*64 + nt*8 + 2*tig;
            float ny0 = s_ny[col], ny1 = s_ny[col + 1];
            int rlo = row0 + wm*32 + mt*16 + g;
            float2 vlo, vhi;
            float d0 = fmaxf(nxv[mt][0]*ny0, 1e-8f);
            float d1 = fmaxf(nxv[mt][0]*ny1, 1e-8f);
            vlo.x = __expf(-INV_EPS * (1.f - acc[mt][nt][0] / d0));
            vlo.y = __expf(-INV_EPS * (1.f - acc[mt][nt][1] / d1));
            float e0 = fmaxf(nxv[mt][1]*ny0, 1e-8f);
            float e1 = fmaxf(nxv[mt][1]*ny1, 1e-8f);
            vhi.x = __expf(-INV_EPS * (1.f - acc[mt][nt][2] / e0));
            vhi.y = __expf(-INV_EPS * (1.f - acc[mt][nt][3] / e1));
            __stcg((float2*)(Kb + ((size_t)rlo       << 10) + col0 + col), vlo);
            __stcg((float2*)(Kb + ((size_t)(rlo + 8) << 10) + col0 + col), vhi);
        }
    }
}

// ---------------------------------------------------------------------------
__global__ void __launch_bounds__(256, 1)
mega_kernel(const float* __restrict__ x, const float* __restrict__ y,
            const float* __restrict__ nu, float* __restrict__ out) {
    extern __shared__ float sm[];            // 72KB: gemm buffers / s_eu reuse
    __shared__ float s_ny[128];
    __shared__ float s_red[8][33];
    __shared__ float s_err;

    const int tid  = threadIdx.x;
    const int lane = tid & 31;
    const int wid  = tid >> 5;
    const int bid  = blockIdx.x;

    // ---------------- phase 0: init + norms ----------------
    {
        int gtid = bid * 256 + tid;          // 0..32767
        if (gtid < BB*NN) {
            g_u[gtid] = 0.f;
            __stcg(&g_eu[gtid], 1.f);
            __stcg(&g_ev[gtid], 1.f);
        }
        if (gtid < NITER) __stcg(&g_err[gtid], 0.f);
        if (gtid < BB)    __stcg(&out[gtid], 0.f);

        int warpG = bid * 8 + wid;           // 0..1023
        #pragma unroll
        for (int q = 0; q < 8; q++) {
            int r = warpG + (q << 10);       // 0..8191
            const float4* src = (r < BB*NN)
                ? (const float4*)(x + (size_t)r * DD)
                : (const float4*)(y + (size_t)(r - BB*NN) * DD);
            float s = 0.f;
            #pragma unroll
            for (int i = 0; i < 4; i++) {
                float4 v = __ldg(&src[lane + 32*i]);
                s += v.x*v.x + v.y*v.y + v.z*v.z + v.w*v.w;
            }
            #pragma unroll
            for (int o = 16; o; o >>= 1) s += __shfl_xor_sync(0xffffffffu, s, o);
            if (lane == 0) {
                float nrm = sqrtf(s);
                if (r < BB*NN) __stcg(&g_nx[r], nrm);
                else           __stcg(&g_ny[r - BB*NN], nrm);
            }
        }
    }
    grid_sync();

    // ---------------- phase 1: GEMM (2 tiles per CTA) ----------------
    #pragma unroll
    for (int t2 = 0; t2 < 2; t2++) {
        int t    = bid + (t2 << 7);          // 0..255
        int col0 = (t & 7) << 7;
        int row0 = ((t >> 3) & 7) << 7;
        int b    = t >> 6;
        gemm_tile(x, y, b, row0, col0, sm, s_ny);
    }
    grid_sync();

    // ---------------- phase 2: Sinkhorn iterations ----------------
    const int warpG = bid * 8 + wid;         // 0..1023
    const int rbase = warpG << 2;            // 4 rows per warp
    const int rb    = rbase >> 10;           // batch of my rows
    const int cb    = bid >> 5;              // batch of my column stripe
    const int j0    = (bid & 31) << 5;       // 32 columns per CTA
    const float LOGMU = logf(1.0f / (float)NN + 1e-8f);
    float lognu = 0.f;
    if (tid < 32) lognu = __logf(__ldg(&nu[(cb << 10) + j0 + tid]) + 1e-8f);
    float* s_eu = sm;                        // 1024 floats, reuses gemm smem

    for (int it = 0; it < NITER; it++) {
        if (tid == 0) s_err = 0.f;
        __syncthreads();

        // ---- row pass: u update ----
        {
            const float4* evp = (const float4*)(g_ev + (rb << 10));
            float4 evr[8];
            #pragma unroll
            for (int i = 0; i < 8; i++) evr[i] = __ldcg(&evp[lane + 32*i]);
            float myerr = 0.f;
            #pragma unroll
            for (int rr = 0; rr < 4; rr++) {
                int r = rbase + rr;
                const float4* Kp = (const float4*)(g_K + ((size_t)r << 10));
                float s = 0.f;
                #pragma unroll
                for (int i = 0; i < 8; i++) {
                    float4 k4 = __ldg(&Kp[lane + 32*i]);
                    s += k4.x*evr[i].x + k4.y*evr[i].y + k4.z*evr[i].z + k4.w*evr[i].w;
                }
                #pragma unroll
                for (int o = 16; o; o >>= 1) s += __shfl_xor_sync(0xffffffffu, s, o);
                if (lane == 0) {
                    float u_old = g_u[r];
                    float u_new = EPSI * LOGMU - EPSI * __logf(s);
                    myerr += fabsf(u_new - u_old);
                    g_u[r] = u_new;
                    __stcg(&g_eu[r], __expf(u_new * INV_EPS));
                }
            }
            if (lane == 0) atomicAdd(&s_err, myerr);
        }
        __syncthreads();
        if (tid == 0) atomicAdd(&g_err[it], s_err);
        grid_sync();

        // ---- col pass: v update ----
        {
            ((float4*)s_eu)[tid] = __ldcg((const float4*)(g_eu + (cb << 10)) + tid);
            __syncthreads();
            const int c = tid & 31, g = tid >> 5;
            const float* Kb = g_K + ((size_t)cb << 20) + j0 + c;
            float s = 0.f;
            #pragma unroll 8
            for (int i = g; i < NN; i += 8)
                s += __ldg(&Kb[(size_t)i << 10]) * s_eu[i];
            s_red[g][c] = s;
            __syncthreads();
            if (g == 0) {
                float tot = 0.f;
                #pragma unroll
                for (int q = 0; q < 8; q++) tot += s_red[q][c];
                float v_new = EPSI * lognu - EPSI * __logf(tot);
                __stcg(&g_ev[(cb << 10) + j0 + c], __expf(v_new * INV_EPS));
            }
        }
        grid_sync();
        if (__ldcg(&g_err[it]) < ERR_THRESH_TOTAL) break;   // uniform across grid
    }

    // ---------------- phase 3: cost = sum_ij C*K*eu_i*ev_j, C = -eps*lnK ----
    {
        __syncthreads();
        ((float4*)s_eu)[tid] = __ldcg((const float4*)(g_eu + (cb << 10)) + tid);
        __syncthreads();
        const int c = tid & 31, g = tid >> 5;
        const float* Kb = g_K + ((size_t)cb << 20) + j0 + c;
        float s = 0.f;
        #pragma unroll 8
        for (int i = g; i < NN; i += 8) {
            float kv = __ldg(&Kb[(size_t)i << 10]);
            s += kv * __logf(kv) * s_eu[i];
        }
        s_red[g][c] = s;
        __syncthreads();
        if (g == 0) {
            float tot = 0.f;
            #pragma unroll
            for (int q = 0; q < 8; q++) tot += s_red[q][c];
            float evj = __ldcg(&g_ev[(cb << 10) + j0 + c]);
            float contrib = -EPSI * tot * evj;
            #pragma unroll
            for (int o = 16; o; o >>= 1) contrib += __shfl_xor_sync(0xffffffffu, contrib, o);
            if (c == 0) atomicAdd(out + cb, contrib);
        }
    }
}

// ---------------------------------------------------------------------------
extern "C" void kernel_launch(void* const* d_in, const int* in_sizes, int n_in,
                              void* d_out, int out_size) {
    const float* x  = (const float*)d_in[0];   // [B,N,D]
    const float* y  = (const float*)d_in[1];   // [B,M,D]
    const float* nu = (const float*)d_in[2];   // [B,M]
    float* out = (float*)d_out;                // [B]

    const int dyn = 4 * TILE_FLOATS * 4;       // 73728 bytes
    cudaFuncSetAttribute(mega_kernel, cudaFuncAttributeMaxDynamicSharedMemorySize, dyn);
    mega_kernel<<<GRID, 256, dyn>>>(x, y, nu, out);
}

// round 7
// speedup vs baseline: 2.2998x; 1.0900x over previous
#include <cuda_runtime.h>
#include <stdint.h>
#include <math.h>

#define BB 4
#define NN 1024
#define MM 1024
#define DD 512
#define EPSI 0.1f
#define INV_EPS 10.0f
#define NITER 20
#define ERR_THRESH_TOTAL 0.4f   /* 0.1 * B, since err = total/B */
#define GRID 128
#define NTHR 512

// ---- device scratch (allocation-free: __device__ globals) ----
__device__ float g_K[BB*NN*MM];   // exp(-C/eps)
__device__ float g_nx[BB*NN];
__device__ float g_ny[BB*MM];
__device__ float g_u [BB*NN];
__device__ float g_eu[BB*NN];     // exp(u/eps)
__device__ float g_ev[BB*MM];     // exp(v/eps)
__device__ float g_err[NITER];
__device__ unsigned           g_bar_count = 0;
__device__ volatile unsigned  g_bar_gen   = 0;

// ---------------- grid-wide barrier (all GRID CTAs co-resident) ----------------
__device__ __forceinline__ void grid_sync() {
    __syncthreads();
    if (threadIdx.x == 0) {
        __threadfence();
        unsigned gen = g_bar_gen;
        if (atomicAdd(&g_bar_count, 1u) == GRID - 1) {
            g_bar_count = 0;
            __threadfence();
            g_bar_gen = gen + 1;
        } else {
            while (g_bar_gen == gen) __nanosleep(64);
        }
    }
    __syncthreads();
}

// ---------------------------------------------------------------------------
// tf32 mma.sync GEMM tile: CTA 128x128, 16 warps of 32x32, K chunks of 32,
// double-buffered smem (1 sync/chunk), k-permuted layout -> LDS.64 operands,
// raw fp32 bits as tf32 (no cvt).
// ---------------------------------------------------------------------------
#define TSTRIDE 36
#define TILE_FLOATS (128*TSTRIDE)   // 4608 floats per tile buffer

__device__ __forceinline__ void store_perm(uint32_t* dst, int sBase, float4 v) {
    dst[sBase+0] = __float_as_uint(v.x);
    dst[sBase+2] = __float_as_uint(v.y);
    dst[sBase+4] = __float_as_uint(v.z);
    dst[sBase+6] = __float_as_uint(v.w);
}

__device__ void gemm_tile(const float* __restrict__ X, const float* __restrict__ Y,
                          int b, int row0, int col0, float* sm, float* s_ny) {
    const int tid  = threadIdx.x;
    const int lane = tid & 31;
    const int wid  = tid >> 5;
    const int wm   = wid & 3;          // 4x4 warp grid
    const int wn   = wid >> 2;
    const int g    = lane >> 2;
    const int tig  = lane & 3;

    uint32_t* smA[2] = { (uint32_t*)sm,                 (uint32_t*)(sm + 2*TILE_FLOATS) };
    uint32_t* smB[2] = { (uint32_t*)(sm + TILE_FLOATS), (uint32_t*)(sm + 3*TILE_FLOATS) };

    __syncthreads();   // previous phase done before overwriting s_ny/buffers
    if (tid < 128) s_ny[tid] = __ldcg(&g_ny[(b << 10) + col0 + tid]);

    const float* Abase = X + ((size_t)b << 19) + ((size_t)row0 << 9);
    const float* Bbase = Y + ((size_t)b << 19) + ((size_t)col0 << 9);
    const float* gA[2]; const float* gB[2];
    int sBase[2];
    #pragma unroll
    for (int q = 0; q < 2; q++) {
        int idx = tid + (q << 9);      // 0..1023
        int row = idx >> 3, c4 = idx & 7;
        gA[q] = Abase + ((size_t)row << 9) + (c4 << 2);
        gB[q] = Bbase + ((size_t)row << 9) + (c4 << 2);
        sBase[q] = row * TSTRIDE + ((c4 >> 1) << 3) + (c4 & 1);
    }

    float acc[2][4][4];
    #pragma unroll
    for (int mt = 0; mt < 2; mt++)
        #pragma unroll
        for (int nt = 0; nt < 4; nt++)
            #pragma unroll
            for (int j = 0; j < 4; j++) acc[mt][nt][j] = 0.f;

    // prologue: buffer 0
    #pragma unroll
    for (int q = 0; q < 2; q++) {
        store_perm(smA[0], sBase[q], *(const float4*)(gA[q]));
        store_perm(smB[0], sBase[q], *(const float4*)(gB[q]));
    }
    __syncthreads();

    for (int s = 0; s < 16; s++) {
        const int buf = s & 1;
        float4 pa[2], pb[2];
        if (s < 15) {
            int k0 = (s + 1) << 5;
            #pragma unroll
            for (int q = 0; q < 2; q++) {
                pa[q] = *(const float4*)(gA[q] + k0);
                pb[q] = *(const float4*)(gB[q] + k0);
            }
        }
        #pragma unroll
        for (int k8 = 0; k8 < 4; k8++) {
            uint32_t a[2][4];
            #pragma unroll
            for (int mt = 0; mt < 2; mt++) {
                int r = wm*32 + mt*16 + g;
                uint2 lo = *(uint2*)&smA[buf][r*TSTRIDE     + k8*8 + 2*tig];
                uint2 hi = *(uint2*)&smA[buf][(r+8)*TSTRIDE + k8*8 + 2*tig];
                a[mt][0] = lo.x; a[mt][2] = lo.y;
                a[mt][1] = hi.x; a[mt][3] = hi.y;
            }
            #pragma unroll
            for (int nt = 0; nt < 4; nt++) {
                int c = wn*32 + nt*8 + g;
                uint2 bb = *(uint2*)&smB[buf][c*TSTRIDE + k8*8 + 2*tig];
                #pragma unroll
                for (int mt = 0; mt < 2; mt++) {
                    asm volatile(
                        "mma.sync.aligned.m16n8k8.row.col.f32.tf32.tf32.f32 "
                        "{%0,%1,%2,%3}, {%4,%5,%6,%7}, {%8,%9}, {%0,%1,%2,%3};"
                        : "+f"(acc[mt][nt][0]), "+f"(acc[mt][nt][1]),
                          "+f"(acc[mt][nt][2]), "+f"(acc[mt][nt][3])
                        : "r"(a[mt][0]), "r"(a[mt][1]), "r"(a[mt][2]), "r"(a[mt][3]),
                          "r"(bb.x), "r"(bb.y));
                }
            }
        }
        if (s < 15) {
            const int nb = buf ^ 1;
            #pragma unroll
            for (int q = 0; q < 2; q++) {
                store_perm(smA[nb], sBase[q], pa[q]);
                store_perm(smB[nb], sBase[q], pb[q]);
            }
            __syncthreads();
        }
    }

    // epilogue: K = exp(-(1 - dot/max(nx*ny,1e-8))/eps)
    float nxv[2][2];
    #pragma unroll
    for (int mt = 0; mt < 2; mt++) {
        int r = row0 + wm*32 + mt*16 + g;
        nxv[mt][0] = __ldcg(&g_nx[(b << 10) + r]);
        nxv[mt][1] = __ldcg(&g_nx[(b << 10) + r + 8]);
    }
    float* Kb = g_K + ((size_t)b << 20);
    #pragma unroll
    for (int mt = 0; mt < 2; mt++) {
        #pragma unroll
        for (int nt = 0; nt < 4; nt++) {
            int col = wn*32 + nt*8 + 2*tig;
            float ny0 = s_ny[col], ny1 = s_ny[col + 1];
            int rlo = row0 + wm*32 + mt*16 + g;
            float2 vlo, vhi;
            float d0 = fmaxf(nxv[mt][0]*ny0, 1e-8f);
            float d1 = fmaxf(nxv[mt][0]*ny1, 1e-8f);
            vlo.x = __expf(-INV_EPS * (1.f - acc[mt][nt][0] / d0));
            vlo.y = __expf(-INV_EPS * (1.f - acc[mt][nt][1] / d1));
            float e0 = fmaxf(nxv[mt][1]*ny0, 1e-8f);
            float e1 = fmaxf(nxv[mt][1]*ny1, 1e-8f);
            vhi.x = __expf(-INV_EPS * (1.f - acc[mt][nt][2] / e0));
            vhi.y = __expf(-INV_EPS * (1.f - acc[mt][nt][3] / e1));
            __stcg((float2*)(Kb + ((size_t)rlo       << 10) + col0 + col), vlo);
            __stcg((float2*)(Kb + ((size_t)(rlo + 8) << 10) + col0 + col), vhi);
        }
    }
}

// ---------------------------------------------------------------------------
__global__ void __launch_bounds__(NTHR, 1)
mega_kernel(const float* __restrict__ x, const float* __restrict__ y,
            const float* __restrict__ nu, float* __restrict__ out) {
    extern __shared__ float sm[];            // 72KB: gemm buffers / s_eu reuse
    __shared__ float s_ny[128];
    __shared__ float s_red[16][33];
    __shared__ float s_err;

    const int tid  = threadIdx.x;
    const int lane = tid & 31;
    const int wid  = tid >> 5;               // 0..15
    const int bid  = blockIdx.x;

    // ---------------- phase 0: init + norms ----------------
    {
        int gtid = bid * NTHR + tid;         // 0..65535
        if (gtid < BB*NN) {
            g_u[gtid] = 0.f;
            __stcg(&g_eu[gtid], 1.f);
            __stcg(&g_ev[gtid], 1.f);
        }
        if (gtid < NITER) __stcg(&g_err[gtid], 0.f);
        if (gtid < BB)    __stcg(&out[gtid], 0.f);

        int warpG = bid * 16 + wid;          // 0..2047
        #pragma unroll
        for (int q = 0; q < 4; q++) {
            int r = warpG + (q << 11);       // 0..8191
            const float4* src = (r < BB*NN)
                ? (const float4*)(x + (size_t)r * DD)
                : (const float4*)(y + (size_t)(r - BB*NN) * DD);
            float s = 0.f;
            #pragma unroll
            for (int i = 0; i < 4; i++) {
                float4 v = __ldg(&src[lane + 32*i]);
                s += v.x*v.x + v.y*v.y + v.z*v.z + v.w*v.w;
            }
            #pragma unroll
            for (int o = 16; o; o >>= 1) s += __shfl_xor_sync(0xffffffffu, s, o);
            if (lane == 0) {
                float nrm = sqrtf(s);
                if (r < BB*NN) __stcg(&g_nx[r], nrm);
                else           __stcg(&g_ny[r - BB*NN], nrm);
            }
        }
    }
    grid_sync();

    // ---------------- phase 1: GEMM (2 tiles per CTA) ----------------
    #pragma unroll
    for (int t2 = 0; t2 < 2; t2++) {
        int t    = bid + (t2 << 7);          // 0..255
        int col0 = (t & 7) << 7;
        int row0 = ((t >> 3) & 7) << 7;
        int b    = t >> 6;
        gemm_tile(x, y, b, row0, col0, sm, s_ny);
    }
    grid_sync();

    // ---------------- phase 2: Sinkhorn iterations ----------------
    const int warpG = bid * 16 + wid;        // 0..2047
    const int rbase = warpG << 1;            // 2 rows per warp
    const int rb    = rbase >> 10;           // batch of my rows
    const int cb    = bid >> 5;              // batch of my column stripe
    const int j0    = (bid & 31) << 5;       // 32 columns per CTA
    const float LOGMU = logf(1.0f / (float)NN + 1e-8f);
    float lognu = 0.f;
    if (tid < 32) lognu = __logf(__ldg(&nu[(cb << 10) + j0 + tid]) + 1e-8f);
    float* s_eu = sm;                        // 1024 floats, reuses gemm smem

    for (int it = 0; it < NITER; it++) {
        if (tid == 0) s_err = 0.f;
        __syncthreads();

        // ---- row pass: u update ----
        {
            const float4* evp = (const float4*)(g_ev + (rb << 10));
            float4 evr[8];
            #pragma unroll
            for (int i = 0; i < 8; i++) evr[i] = __ldcg(&evp[lane + 32*i]);
            float myerr = 0.f;
            #pragma unroll
            for (int rr = 0; rr < 2; rr++) {
                int r = rbase + rr;
                const float4* Kp = (const float4*)(g_K + ((size_t)r << 10));
                float s = 0.f;
                #pragma unroll
                for (int i = 0; i < 8; i++) {
                    float4 k4 = __ldg(&Kp[lane + 32*i]);
                    s += k4.x*evr[i].x + k4.y*evr[i].y + k4.z*evr[i].z + k4.w*evr[i].w;
                }
                #pragma unroll
                for (int o = 16; o; o >>= 1) s += __shfl_xor_sync(0xffffffffu, s, o);
                if (lane == 0) {
                    float u_old = g_u[r];
                    float u_new = EPSI * LOGMU - EPSI * __logf(s);
                    myerr += fabsf(u_new - u_old);
                    g_u[r] = u_new;
                    __stcg(&g_eu[r], __expf(u_new * INV_EPS));
                }
            }
            if (lane == 0) atomicAdd(&s_err, myerr);
        }
        __syncthreads();
        if (tid == 0) atomicAdd(&g_err[it], s_err);
        grid_sync();

        // ---- col pass: v update ----
        {
            if (tid < 256) ((float4*)s_eu)[tid] = __ldcg((const float4*)(g_eu + (cb << 10)) + tid);
            __syncthreads();
            const int c = tid & 31, g = tid >> 5;     // g = 0..15
            const float* Kb = g_K + ((size_t)cb << 20) + j0 + c;
            float s = 0.f;
            #pragma unroll 8
            for (int i = g; i < NN; i += 16)
                s += __ldg(&Kb[(size_t)i << 10]) * s_eu[i];
            s_red[g][c] = s;
            __syncthreads();
            if (g == 0) {
                float tot = 0.f;
                #pragma unroll
                for (int q = 0; q < 16; q++) tot += s_red[q][c];
                float v_new = EPSI * lognu - EPSI * __logf(tot);
                __stcg(&g_ev[(cb << 10) + j0 + c], __expf(v_new * INV_EPS));
            }
        }
        grid_sync();
        if (__ldcg(&g_err[it]) < ERR_THRESH_TOTAL) break;   // uniform across grid
    }

    // ---------------- phase 3: cost = sum_ij C*K*eu_i*ev_j, C = -eps*lnK ----
    {
        __syncthreads();
        if (tid < 256) ((float4*)s_eu)[tid] = __ldcg((const float4*)(g_eu + (cb << 10)) + tid);
        __syncthreads();
        const int c = tid & 31, g = tid >> 5;
        const float* Kb = g_K + ((size_t)cb << 20) + j0 + c;
        float s = 0.f;
        #pragma unroll 8
        for (int i = g; i < NN; i += 16) {
            float kv = __ldg(&Kb[(size_t)i << 10]);
            s += kv * __logf(kv) * s_eu[i];
        }
        s_red[g][c] = s;
        __syncthreads();
        if (g == 0) {
            float tot = 0.f;
            #pragma unroll
            for (int q = 0; q < 16; q++) tot += s_red[q][c];
            float evj = __ldcg(&g_ev[(cb << 10) + j0 + c]);
            float contrib = -EPSI * tot * evj;
            #pragma unroll
            for (int o = 16; o; o >>= 1) contrib += __shfl_xor_sync(0xffffffffu, contrib, o);
            if (c == 0) atomicAdd(out + cb, contrib);
        }
    }
}

// ---------------------------------------------------------------------------
extern "C" void kernel_launch(void* const* d_in, const int* in_sizes, int n_in,
                              void* d_out, int out_size) {
    const float* x  = (const float*)d_in[0];   // [B,N,D]
    const float* y  = (const float*)d_in[1];   // [B,M,D]
    const float* nu = (const float*)d_in[2];   // [B,M]
    float* out = (float*)d_out;                // [B]

    const int dyn = 4 * TILE_FLOATS * 4;       // 73728 bytes
    cudaFuncSetAttribute(mega_kernel, cudaFuncAttributeMaxDynamicSharedMemorySize, dyn);
    mega_kernel<<<GRID, NTHR, dyn>>>(x, y, nu, out);
}